// round 7
// baseline (speedup 1.0000x reference)
#include <cuda_runtime.h>
#include <math.h>

#define H 2048
#define VOC 50257

#define NBLK 592                 // exactly 4 blocks/SM * 148 SMs -> co-resident
#define NTHR 256
#define NWARP (NBLK * 8)         // 4736 warps
#define VITERS ((VOC + NWARP - 1) / NWARP)   // 11

// Phase-1 task layout (chunk = 64 float4 = 256 floats per gate-stream)
#define T_WI1 8192               // 2048 units * 4 chunks   (W_ih1, K=1024)
#define T_WH1 16384              // 2048 units * 8 chunks   (W_hh1, K=2048)
#define T_HH2 16384              // 2048 units * 8 chunks   (W_hh2, K=2048)
#define T1 (T_WI1 + T_WH1 + T_HH2)          // 40960
// Phase-2 task layout (chunk = 32 float4 = 128 floats)
#define T2 32768                 // 2048 units * 16 chunks  (W_ih2, K=2048)

// Scratch (no allocations allowed)
__device__ float g_part[T1 * 4];             // per-task 4-gate partials (reused by P2)
__device__ float g_h1n[H];
__device__ float g_h2n[H];
__device__ float g_gates2[4 * H];
__device__ float g_logits[VOC];
__device__ float g_pm[NBLK];
__device__ float g_ps[NBLK];
__device__ unsigned long long g_ticket = 0;  // monotonic -> replay-safe barrier

__device__ __forceinline__ float warp_sum(float a) {
    #pragma unroll
    for (int o = 16; o > 0; o >>= 1)
        a += __shfl_xor_sync(0xffffffffu, a, o);
    return a;
}
__device__ __forceinline__ float sigmoidf_(float v) {
    return 1.0f / (1.0f + expf(-v));
}

__device__ __forceinline__ void grid_barrier() {
    __syncthreads();
    __threadfence();
    if (threadIdx.x == 0) {
        const unsigned long long my = atomicAdd(&g_ticket, 1ULL);
        const unsigned long long target = (my / NBLK + 1ULL) * NBLK;
        while (atomicAdd(&g_ticket, 0ULL) < target) { }
    }
    __syncthreads();
    __threadfence();
}

__global__ __launch_bounds__(NTHR, 4) void mega_kernel(
    const float* __restrict__ x,     const float* __restrict__ h1,
    const float* __restrict__ c1,    const float* __restrict__ h2,
    const float* __restrict__ c2,
    const float* __restrict__ W_ih1, const float* __restrict__ W_hh1,
    const float* __restrict__ b_ih1, const float* __restrict__ b_hh1,
    const float* __restrict__ W_ih2, const float* __restrict__ W_hh2,
    const float* __restrict__ b_ih2, const float* __restrict__ b_hh2,
    const float* __restrict__ W_out, const float* __restrict__ b_out,
    float* __restrict__ out)
{
    __shared__ float sbuf[5120];     // P1: x|h1|h2 ; P2: h1n ; P3: h2n
    __shared__ float swm[8];
    __shared__ float sws[8];
    __shared__ float sred[256];

    const int tid   = threadIdx.x;
    const int wid   = tid >> 5;
    const int lane  = tid & 31;
    const int wglob = blockIdx.x * 8 + wid;

    // ============================ PHASE 1 ================================
    // stage x (1024), h1 (2048), h2 (2048)
    for (int i = tid; i < 1024; i += NTHR) sbuf[i]        = x[i];
    for (int i = tid; i < 2048; i += NTHR) sbuf[1024 + i] = h1[i];
    for (int i = tid; i < 2048; i += NTHR) sbuf[3072 + i] = h2[i];
    __syncthreads();

    const float4* sx4  = (const float4*)(sbuf);
    const float4* sh14 = (const float4*)(sbuf + 1024);
    const float4* sh24 = (const float4*)(sbuf + 3072);

    for (int t = wglob; t < T1; t += NWARP) {
        const float*  Wb;
        const float4* vec;
        int u, ch, kf4;
        if (t < T_WI1)              { u = t >> 2;            ch = t & 3;            Wb = W_ih1; vec = sx4;  kf4 = 256; }
        else if (t < T_WI1 + T_WH1) { u = (t - T_WI1) >> 3;  ch = (t - T_WI1) & 7;  Wb = W_hh1; vec = sh14; kf4 = 512; }
        else                        { const int tt = t - T_WI1 - T_WH1;
                                      u = tt >> 3;           ch = tt & 7;           Wb = W_hh2; vec = sh24; kf4 = 512; }

        const float4* w0 = (const float4*)Wb + (size_t)(u        ) * kf4;
        const float4* w1 = (const float4*)Wb + (size_t)(u +     H) * kf4;
        const float4* w2 = (const float4*)Wb + (size_t)(u + 2 * H) * kf4;
        const float4* w3 = (const float4*)Wb + (size_t)(u + 3 * H) * kf4;

        const int j0 = ch * 64 + lane;
        const int j1 = j0 + 32;
        const float4 v0 = vec[j0], v1 = vec[j1];
        const float4 p00 = __ldcs(&w0[j0]), p01 = __ldcs(&w0[j1]);
        const float4 p10 = __ldcs(&w1[j0]), p11 = __ldcs(&w1[j1]);
        const float4 p20 = __ldcs(&w2[j0]), p21 = __ldcs(&w2[j1]);
        const float4 p30 = __ldcs(&w3[j0]), p31 = __ldcs(&w3[j1]);

        float a0 = p00.x*v0.x + p00.y*v0.y + p00.z*v0.z + p00.w*v0.w
                 + p01.x*v1.x + p01.y*v1.y + p01.z*v1.z + p01.w*v1.w;
        float a1 = p10.x*v0.x + p10.y*v0.y + p10.z*v0.z + p10.w*v0.w
                 + p11.x*v1.x + p11.y*v1.y + p11.z*v1.z + p11.w*v1.w;
        float a2 = p20.x*v0.x + p20.y*v0.y + p20.z*v0.z + p20.w*v0.w
                 + p21.x*v1.x + p21.y*v1.y + p21.z*v1.z + p21.w*v1.w;
        float a3 = p30.x*v0.x + p30.y*v0.y + p30.z*v0.z + p30.w*v0.w
                 + p31.x*v1.x + p31.y*v1.y + p31.z*v1.z + p31.w*v1.w;

        a0 = warp_sum(a0); a1 = warp_sum(a1); a2 = warp_sum(a2); a3 = warp_sum(a3);
        if (lane == 0) {
            float* d = &g_part[(size_t)t * 4];
            d[0] = a0; d[1] = a1; d[2] = a2; d[3] = a3;
        }
    }

    grid_barrier();   // g_part complete

    // ============================ PHASE 1b ===============================
    if (wglob < 2048) {
        const int u = wglob;
        // layer-1 unit: 4 wi partials (lane<4) + 8 wh partials (lane 4..11)
        int tp = -1;
        if (lane < 4)       tp = u * 4 + lane;
        else if (lane < 12) tp = T_WI1 + u * 8 + (lane - 4);
        float s0 = 0.f, s1 = 0.f, s2 = 0.f, s3 = 0.f;
        if (tp >= 0) {
            const float* d = &g_part[(size_t)tp * 4];
            s0 = d[0]; s1 = d[1]; s2 = d[2]; s3 = d[3];
        }
        s0 = warp_sum(s0); s1 = warp_sum(s1); s2 = warp_sum(s2); s3 = warp_sum(s3);
        if (lane == 0) {
            const float gi = s0 + b_ih1[u        ] + b_hh1[u        ];
            const float gf = s1 + b_ih1[u +     H] + b_hh1[u +     H];
            const float gg = s2 + b_ih1[u + 2 * H] + b_hh1[u + 2 * H];
            const float go = s3 + b_ih1[u + 3 * H] + b_hh1[u + 3 * H];
            const float iv = sigmoidf_(gi), fv = sigmoidf_(gf);
            const float gv = tanhf(gg),     ov = sigmoidf_(go);
            const float cn = fv * c1[u] + iv * gv;
            g_h1n[u] = ov * tanhf(cn);
        }
    } else if (wglob < 4096) {
        const int u = wglob - 2048;
        float s0 = 0.f, s1 = 0.f, s2 = 0.f, s3 = 0.f;
        if (lane < 8) {
            const float* d = &g_part[(size_t)(T_WI1 + T_WH1 + u * 8 + lane) * 4];
            s0 = d[0]; s1 = d[1]; s2 = d[2]; s3 = d[3];
        }
        s0 = warp_sum(s0); s1 = warp_sum(s1); s2 = warp_sum(s2); s3 = warp_sum(s3);
        if (lane == 0) {
            g_gates2[u        ] = s0 + b_ih2[u        ] + b_hh2[u        ];
            g_gates2[u +     H] = s1 + b_ih2[u +     H] + b_hh2[u +     H];
            g_gates2[u + 2 * H] = s2 + b_ih2[u + 2 * H] + b_hh2[u + 2 * H];
            g_gates2[u + 3 * H] = s3 + b_ih2[u + 3 * H] + b_hh2[u + 3 * H];
        }
    }

    grid_barrier();   // h1n + gates2 ready; g_part free for reuse

    // ============================ PHASE 2 ================================
    for (int i = tid; i < 2048; i += NTHR) sbuf[i] = g_h1n[i];
    __syncthreads();
    const float4* sg4 = (const float4*)sbuf;

    for (int t = wglob; t < T2; t += NWARP) {
        const int u  = t >> 4;
        const int ch = t & 15;
        const float4* w0 = (const float4*)W_ih2 + (size_t)(u        ) * 512;
        const float4* w1 = (const float4*)W_ih2 + (size_t)(u +     H) * 512;
        const float4* w2 = (const float4*)W_ih2 + (size_t)(u + 2 * H) * 512;
        const float4* w3 = (const float4*)W_ih2 + (size_t)(u + 3 * H) * 512;

        const int j = ch * 32 + lane;
        const float4 v  = sg4[j];
        const float4 p0 = __ldcs(&w0[j]);
        const float4 p1 = __ldcs(&w1[j]);
        const float4 p2 = __ldcs(&w2[j]);
        const float4 p3 = __ldcs(&w3[j]);

        float a0 = p0.x*v.x + p0.y*v.y + p0.z*v.z + p0.w*v.w;
        float a1 = p1.x*v.x + p1.y*v.y + p1.z*v.z + p1.w*v.w;
        float a2 = p2.x*v.x + p2.y*v.y + p2.z*v.z + p2.w*v.w;
        float a3 = p3.x*v.x + p3.y*v.y + p3.z*v.z + p3.w*v.w;

        a0 = warp_sum(a0); a1 = warp_sum(a1); a2 = warp_sum(a2); a3 = warp_sum(a3);
        if (lane == 0) {
            float* d = &g_part[(size_t)t * 4];
            d[0] = a0; d[1] = a1; d[2] = a2; d[3] = a3;
        }
    }

    grid_barrier();   // P2 partials complete

    // ============================ PHASE 2b ===============================
    if (wglob < 2048) {
        const int u = wglob;
        float s0 = 0.f, s1 = 0.f, s2 = 0.f, s3 = 0.f;
        if (lane < 16) {
            const float* d = &g_part[(size_t)(u * 16 + lane) * 4];
            s0 = d[0]; s1 = d[1]; s2 = d[2]; s3 = d[3];
        }
        s0 = warp_sum(s0); s1 = warp_sum(s1); s2 = warp_sum(s2); s3 = warp_sum(s3);
        if (lane == 0) {
            const float gi = s0 + g_gates2[u        ];
            const float gf = s1 + g_gates2[u +     H];
            const float gg = s2 + g_gates2[u + 2 * H];
            const float go = s3 + g_gates2[u + 3 * H];
            const float iv = sigmoidf_(gi), fv = sigmoidf_(gf);
            const float gv = tanhf(gg),     ov = sigmoidf_(go);
            const float cn = fv * c2[u] + iv * gv;
            g_h2n[u] = ov * tanhf(cn);
        }
    }

    grid_barrier();   // h2n ready

    // ============================ PHASE 3 ================================
    __syncthreads();
    for (int i = tid; i < 2048; i += NTHR) sbuf[i] = g_h2n[i];
    __syncthreads();
    const float4* sh4 = (const float4*)sbuf;

    float m = -INFINITY, s = 0.0f;
    for (int it = 0; it < VITERS; it++) {
        const int row = wglob + it * NWARP;
        if (row < VOC) {
            const float4* w4 = (const float4*)(W_out + (size_t)row * 2048);
            float a = 0.0f;
            #pragma unroll 8
            for (int j = lane; j < 512; j += 32) {
                float4 wv = __ldcs(&w4[j]); float4 hv = sh4[j];
                a += wv.x * hv.x + wv.y * hv.y + wv.z * hv.z + wv.w * hv.w;
            }
            a = warp_sum(a);
            const float v = a + __ldg(&b_out[row]);
            if (lane == 0) g_logits[row] = v;
            const float nm = fmaxf(m, v);
            s = s * expf(m - nm) + expf(v - nm);
            m = nm;
        }
    }
    if (lane == 0) { swm[wid] = m; sws[wid] = s; }
    __syncthreads();

    if (tid == 0) {
        float bm = -INFINITY;
        #pragma unroll
        for (int i = 0; i < 8; i++) bm = fmaxf(bm, swm[i]);
        float bs = 0.0f;
        #pragma unroll
        for (int i = 0; i < 8; i++)
            bs += (swm[i] == -INFINITY) ? 0.0f : sws[i] * expf(swm[i] - bm);
        g_pm[blockIdx.x] = bm;
        g_ps[blockIdx.x] = bs;
    }

    grid_barrier();   // all (m,s) partials visible

    float lm = -INFINITY;
    for (int i = tid; i < NBLK; i += NTHR) lm = fmaxf(lm, g_pm[i]);
    sred[tid] = lm;
    __syncthreads();
    for (int st = 128; st > 0; st >>= 1) {
        if (tid < st) sred[tid] = fmaxf(sred[tid], sred[tid + st]);
        __syncthreads();
    }
    const float M = sred[0];
    __syncthreads();

    float ls = 0.0f;
    for (int i = tid; i < NBLK; i += NTHR)
        ls += (g_pm[i] == -INFINITY) ? 0.0f : g_ps[i] * expf(g_pm[i] - M);
    sred[tid] = ls;
    __syncthreads();
    for (int st = 128; st > 0; st >>= 1) {
        if (tid < st) sred[tid] += sred[tid + st];
        __syncthreads();
    }
    const float shift = M + logf(sred[0]);

    for (int i = blockIdx.x * NTHR + tid; i < VOC; i += NBLK * NTHR)
        out[i] = g_logits[i] - shift;
}

// ---------------------------------------------------------------------------
extern "C" void kernel_launch(void* const* d_in, const int* in_sizes, int n_in,
                              void* d_out, int out_size)
{
    const float* x     = (const float*)d_in[0];
    const float* h1    = (const float*)d_in[1];
    const float* c1    = (const float*)d_in[2];
    const float* h2    = (const float*)d_in[3];
    const float* c2    = (const float*)d_in[4];
    const float* W_ih1 = (const float*)d_in[5];
    const float* W_hh1 = (const float*)d_in[6];
    const float* b_ih1 = (const float*)d_in[7];
    const float* b_hh1 = (const float*)d_in[8];
    const float* W_ih2 = (const float*)d_in[9];
    const float* W_hh2 = (const float*)d_in[10];
    const float* b_ih2 = (const float*)d_in[11];
    const float* b_hh2 = (const float*)d_in[12];
    const float* W_out = (const float*)d_in[13];
    const float* b_out = (const float*)d_in[14];
    float* out = (float*)d_out;

    mega_kernel<<<NBLK, NTHR>>>(x, h1, c1, h2, c2,
                                W_ih1, W_hh1, b_ih1, b_hh1,
                                W_ih2, W_hh2, b_ih2, b_hh2,
                                W_out, b_out, out);
}